// round 17
// baseline (speedup 1.0000x reference)
#include <cuda_runtime.h>
#include <cuda_fp16.h>
#include <stdint.h>

#define P_PTS 200000
#define C_CH  32
#define N_B   4
#define K_FR  8
#define H_IMG 256
#define W_IMG 256
#define TILE  32                 // pixels per strip (row segment)
#define ROWS  2                  // image rows per block
#define TPR   (W_IMG / TILE)     // 8 strips per image row

// Transposed + fp16 point features: (P, C) half = 64B per point.
__device__ __half2 g_tab2[P_PTS * (C_CH / 2)];   // 12.8 MB

// ---------------------------------------------------------------------------
// Kernel 1: transpose + downconvert ptclds (C,P) f32 -> (P,C) f16.
// ---------------------------------------------------------------------------
__global__ void __launch_bounds__(256) transpose_kernel(const float* __restrict__ ptclds) {
    __shared__ float tile[32][65];   // 32 channels x 64 points, padded
    const int p0  = blockIdx.x * 64;
    const int tid = threadIdx.x;

    {
        const int c   = tid >> 3;
        const int col = (tid & 7) * 8;
        const float4* src = reinterpret_cast<const float4*>(ptclds + c * P_PTS + p0 + col);
        const float4 v0 = src[0];
        const float4 v1 = src[1];
        tile[c][col + 0] = v0.x; tile[c][col + 1] = v0.y;
        tile[c][col + 2] = v0.z; tile[c][col + 3] = v0.w;
        tile[c][col + 4] = v1.x; tile[c][col + 5] = v1.y;
        tile[c][col + 6] = v1.z; tile[c][col + 7] = v1.w;
    }
    __syncthreads();

#pragma unroll
    for (int i = 0; i < 4; i++) {
        const int idx = tid + i * 256;
        const int pl  = idx >> 4;    // point within tile
        const int cp  = idx & 15;    // channel pair
        g_tab2[(p0 + pl) * (C_CH / 2) + cp] =
            __floats2half2_rn(tile[cp * 2][pl], tile[cp * 2 + 1][pl]);
    }
}

// ---------------------------------------------------------------------------
// Kernel 2: composite = R15 (best measured: 22.1us) extended to 2 rows/block.
// R16 lesson: the kernel is latency-exposure-bound; fewer instructions made
// it SLOWER. So double per-warp MLP instead: each warp gathers for 4 pixels
// in BOTH rows -> 16 outstanding LDG.64(cg) to overlap the ~250cyc L2 hits.
// Phase-1 weight precompute runs on 2 warps; barriers amortized over 2 rows.
// ---------------------------------------------------------------------------
__global__ void __launch_bounds__(256) composite_kernel(
    const int*   __restrict__ frags,
    const float* __restrict__ alphas,
    float*       __restrict__ out)
{
    __shared__ int2  s_wp[ROWS][K_FR][TILE];      // packed (wgt bits, quad-ofs)
    __shared__ float s_out[ROWS][C_CH][TILE + 1]; // stride 33: conflict-free

    const int b   = blockIdx.x;
    const int hpb = H_IMG / ROWS;                 // 128 row-pairs per image
    const int n   = b / (hpb * TPR);
    const int rem = b % (hpb * TPR);
    const int h0  = (rem / TPR) * ROWS;
    const int w0  = (rem % TPR) * TILE;

    const int tid = threadIdx.x;

    // Phase 1: warps 0-1 compute per-pixel weights+offsets (one thread per
    // (row, pixel)). Per k, each warp's 32 lanes read consecutive -> coalesced.
    if (tid < ROWS * TILE) {
        const int r  = tid >> 5;          // row 0/1
        const int px = tid & 31;          // pixel in strip
        const int pbase = ((n * K_FR) * H_IMG + h0 + r) * W_IMG + w0 + px;
        float T = 1.0f;
#pragma unroll
        for (int kk = 0; kk < K_FR; kk++) {
            const int   off   = pbase + kk * (H_IMG * W_IMG);
            const int   p     = __ldcs(frags + off);
            const float araw  = __ldcs(alphas + off);
            const bool  valid = (p >= 0);
            const float a     = valid ? araw : 0.0f;
            const float w     = a * T;
            T *= (1.0f - a);
            int pc = valid ? p : 0;
            pc     = (pc < P_PTS) ? pc : (P_PTS - 1);   // safety clamp
            s_wp[r][kk][px] = make_int2(__float_as_int(w), pc * (C_CH / 4));
        }
    }
    __syncthreads();

    const int lane = tid & 31;
    const int wid  = tid >> 5;               // warp id 0..7
    const int pi   = wid * 4 + (lane >> 3);  // pixel within 32-pixel strip
    const int cq   = lane & 7;               // channel quad 0..7

    // Phase 2: 16 independent L1-bypassed LDG.64 gathers (8 per row) + FMA.
    const uint2* __restrict__ tab = reinterpret_cast<const uint2*>(g_tab2);
    float4 acc0 = make_float4(0.0f, 0.0f, 0.0f, 0.0f);
    float4 acc1 = make_float4(0.0f, 0.0f, 0.0f, 0.0f);
#pragma unroll
    for (int kk = 0; kk < K_FR; kk++) {
        const int2  wpA = s_wp[0][kk][pi];        // broadcast LDS.64
        const int2  wpB = s_wp[1][kk][pi];
        const uint2 rA  = __ldcg(tab + wpA.y + cq);
        const uint2 rB  = __ldcg(tab + wpB.y + cq);

        const float  wA  = __int_as_float(wpA.x);
        const float2 a01 = __half22float2(*reinterpret_cast<const __half2*>(&rA.x));
        const float2 a23 = __half22float2(*reinterpret_cast<const __half2*>(&rA.y));
        acc0.x += wA * a01.x;  acc0.y += wA * a01.y;
        acc0.z += wA * a23.x;  acc0.w += wA * a23.y;

        const float  wB  = __int_as_float(wpB.x);
        const float2 b01 = __half22float2(*reinterpret_cast<const __half2*>(&rB.x));
        const float2 b23 = __half22float2(*reinterpret_cast<const __half2*>(&rB.y));
        acc1.x += wB * b01.x;  acc1.y += wB * b01.y;
        acc1.z += wB * b23.x;  acc1.w += wB * b23.y;
    }

    // Scatter: banks (4cq + j + pi) mod 32 distinct per warp -> conflict-free.
    s_out[0][cq * 4 + 0][pi] = acc0.x;
    s_out[0][cq * 4 + 1][pi] = acc0.y;
    s_out[0][cq * 4 + 2][pi] = acc0.z;
    s_out[0][cq * 4 + 3][pi] = acc0.w;
    s_out[1][cq * 4 + 0][pi] = acc1.x;
    s_out[1][cq * 4 + 1][pi] = acc1.y;
    s_out[1][cq * 4 + 2][pi] = acc1.z;
    s_out[1][cq * 4 + 3][pi] = acc1.w;
    __syncthreads();

    // Epilogue: per row, 32 channels x 32 pixels; warps store contiguous 128B.
    // Banks c + pw mod 32 distinct per warp (c fixed, pw = lane).
#pragma unroll
    for (int r = 0; r < ROWS; r++) {
#pragma unroll
        for (int i = 0; i < 4; i++) {
            const int idx = tid + i * 256;
            const int c   = idx >> 5;
            const int pw  = idx & 31;
            __stcs(&out[((n * C_CH + c) * H_IMG + h0 + r) * W_IMG + w0 + pw],
                   s_out[r][c][pw]);
        }
    }
}

extern "C" void kernel_launch(void* const* d_in, const int* in_sizes, int n_in,
                              void* d_out, int out_size) {
    const int*   frags  = (const int*)d_in[0];    // int32 (N,K,H,W)
    const float* alphas = (const float*)d_in[1];  // f32   (N,K,H,W)
    const float* ptclds = (const float*)d_in[2];  // f32   (C,P)
    float*       out    = (float*)d_out;          // f32   (N,C,H,W)

    transpose_kernel<<<P_PTS / 64, 256>>>(ptclds);
    composite_kernel<<<N_B * (H_IMG / ROWS) * TPR, 256>>>(frags, alphas, out);
}